// round 15
// baseline (speedup 1.0000x reference)
#include <cuda_runtime.h>
#include <cuda_bf16.h>
#include <math.h>
#include <cstdint>

#define NMAX 50000
#define EMAX 640000
#define BUCK 64   // per-node CSR bucket capacity (max degree ~35 for this graph)

// Scratch (static device arrays: allocation-free per harness rules)
__device__ int   g_cursor[NMAX];        // bucket fill cursors; end of row after fill
__device__ int   g_csr[NMAX * BUCK];    // src indices, bucketed by dst
__device__ float g_xs[NMAX * 128];      // (x@W1) * dinv[row]
__device__ float g_hs[NMAX * 40];       // (relu(...)@W2) * dinv[row]
// W1 split-bf16, [half][n][72] padded (stride 72 b16 = 36 words -> banks 4n+(l&3))
__device__ __align__(16) unsigned short g_Whi[2 * 128 * 72];
__device__ __align__(16) unsigned short g_Wlo[2 * 128 * 72];

// ---------------------------------------------------------------------------
// preamble: init cursors, then scatter edges into per-dst buckets
// ---------------------------------------------------------------------------
__global__ void k_init(int n) {
    int i = blockIdx.x * blockDim.x + threadIdx.x;
    if (i < n) g_cursor[i] = i * BUCK;
}

__global__ void k_fill(const int* __restrict__ ei, int E) {
    int t = blockIdx.x * blockDim.x + threadIdx.x;
    int e0 = t * 2;
    if (e0 >= E) return;
    int e1 = e0 + 1;
    int d0 = ei[E + e0];
    int s0 = ei[e0];
    if (e1 < E) {
        int d1 = ei[E + e1];
        int s1 = ei[e1];
        int p0 = atomicAdd(&g_cursor[d0], 1);
        int p1 = atomicAdd(&g_cursor[d1], 1);
        if (p0 < d0 * BUCK + BUCK) g_csr[p0] = s0;
        if (p1 < d1 * BUCK + BUCK) g_csr[p1] = s1;
    } else {
        int p0 = atomicAdd(&g_cursor[d0], 1);
        if (p0 < d0 * BUCK + BUCK) g_csr[p0] = s0;
    }
}

// ---------------------------------------------------------------------------
// prep: W1[k][n] f32 -> split bf16 hi/lo in padded [k>>6][n][k&63] layout
// ---------------------------------------------------------------------------
__global__ void k_prepW(const float* __restrict__ W) {
    int idx = blockIdx.x * blockDim.x + threadIdx.x;
    if (idx >= 128 * 128) return;
    int k = idx >> 7, n = idx & 127;
    float v = W[idx];
    __nv_bfloat16 h = __float2bfloat16(v);
    __nv_bfloat16 l = __float2bfloat16(v - __bfloat162float(h));
    int a = (k >> 6) * (128 * 72) + n * 72 + (k & 63);
    g_Whi[a] = *(unsigned short*)&h;
    g_Wlo[a] = *(unsigned short*)&l;
}

// ---------------------------------------------------------------------------
// GEMM1 via mma.sync bf16 (split hi/lo, fp32 accum => fp32-level accuracy):
//   xs = (x @ W1) * dinv[row]
// 128 threads / 4 warps; block M-tile 64 (warp m16), N=128 (16 n8 tiles),
// K processed in two halves of 64 (W half staged in smem).
// ---------------------------------------------------------------------------
__device__ __forceinline__ void mma_bf16(float* c, const uint32_t* a,
                                         uint32_t b0, uint32_t b1) {
    asm volatile(
        "mma.sync.aligned.m16n8k16.row.col.f32.bf16.bf16.f32 "
        "{%0,%1,%2,%3}, {%4,%5,%6,%7}, {%8,%9}, {%0,%1,%2,%3};"
        : "+f"(c[0]), "+f"(c[1]), "+f"(c[2]), "+f"(c[3])
        : "r"(a[0]), "r"(a[1]), "r"(a[2]), "r"(a[3]), "r"(b0), "r"(b1));
}

__device__ __forceinline__ uint32_t cvt_hi(float2 f, float2& rem) {
    __nv_bfloat162 b = __floats2bfloat162_rn(f.x, f.y);
    float2 bf = __bfloat1622float2(b);
    rem = make_float2(f.x - bf.x, f.y - bf.y);
    return *(uint32_t*)&b;
}
__device__ __forceinline__ uint32_t cvt_lo(float2 rem) {
    __nv_bfloat162 b = __floats2bfloat162_rn(rem.x, rem.y);
    return *(uint32_t*)&b;
}

__global__ void __launch_bounds__(128)
k_gemm1_mma(const float* __restrict__ x, int nrows) {
    __shared__ unsigned short sWhi[128 * 72];  // 18KB
    __shared__ unsigned short sWlo[128 * 72];  // 18KB
    int tid = threadIdx.x;
    int w = tid >> 5, lane = tid & 31;
    int qr = lane >> 2, qc = lane & 3;      // quad row / col within fragment
    int mBase = blockIdx.x * 64 + w * 16;
    int row0 = mBase + qr, row1 = row0 + 8;
    bool v0 = row0 < nrows, v1 = row1 < nrows;

    float acc[16][4];
#pragma unroll
    for (int t = 0; t < 16; t++)
#pragma unroll
        for (int i = 0; i < 4; i++) acc[t][i] = 0.f;

    const float2* X2 = (const float2*)x;  // 64 float2 per row

    for (int kh = 0; kh < 2; kh++) {
        if (kh) __syncthreads();
        {   // stage W half into smem (raw uint4 copy of padded layout)
            const uint4* shi = (const uint4*)(g_Whi + kh * (128 * 72));
            const uint4* slo = (const uint4*)(g_Wlo + kh * (128 * 72));
            uint4* dhi = (uint4*)sWhi;
            uint4* dlo = (uint4*)sWlo;
            for (int i = tid; i < 128 * 72 / 8; i += 128) {
                dhi[i] = shi[i];
                dlo[i] = slo[i];
            }
        }
        __syncthreads();

#pragma unroll
        for (int k16 = 0; k16 < 4; k16++) {
            int kb = kh * 64 + k16 * 16;
            int c0 = (kb + qc * 2) >> 1;   // float2 index
            int c1 = c0 + 4;
            float2 f0 = v0 ? X2[row0 * 64 + c0] : make_float2(0.f, 0.f);
            float2 f1 = v1 ? X2[row1 * 64 + c0] : make_float2(0.f, 0.f);
            float2 f2 = v0 ? X2[row0 * 64 + c1] : make_float2(0.f, 0.f);
            float2 f3 = v1 ? X2[row1 * 64 + c1] : make_float2(0.f, 0.f);
            uint32_t ahi[4], alo[4];
            float2 r0, r1, r2, r3;
            ahi[0] = cvt_hi(f0, r0);
            ahi[1] = cvt_hi(f1, r1);
            ahi[2] = cvt_hi(f2, r2);
            ahi[3] = cvt_hi(f3, r3);
            alo[0] = cvt_lo(r0);
            alo[1] = cvt_lo(r1);
            alo[2] = cvt_lo(r2);
            alo[3] = cvt_lo(r3);

            int kk = k16 * 16 + qc * 2;  // b16 offset within half-row
#pragma unroll
            for (int t = 0; t < 16; t++) {
                int n = t * 8 + qr;
                const unsigned short* ph = sWhi + n * 72 + kk;
                const unsigned short* pl = sWlo + n * 72 + kk;
                uint32_t bh0 = *(const uint32_t*)ph;
                uint32_t bh1 = *(const uint32_t*)(ph + 8);
                uint32_t bl0 = *(const uint32_t*)pl;
                uint32_t bl1 = *(const uint32_t*)(pl + 8);
                mma_bf16(acc[t], ahi, bh0, bh1);
                mma_bf16(acc[t], alo, bh0, bh1);
                mma_bf16(acc[t], ahi, bl0, bl1);
            }
        }
    }

    // epilogue: scale by dinv, store float2s
    float d0 = 0.f, d1 = 0.f;
    if (v0) d0 = rsqrtf((float)(g_cursor[row0] - row0 * BUCK + 1));
    if (v1) d1 = rsqrtf((float)(g_cursor[row1] - row1 * BUCK + 1));
    float2* xs2 = (float2*)g_xs;
#pragma unroll
    for (int t = 0; t < 16; t++) {
        int col = t * 8 + qc * 2;
        if (v0) xs2[(row0 * 128 + col) >> 1] = make_float2(acc[t][0] * d0, acc[t][1] * d0);
        if (v1) xs2[(row1 * 128 + col) >> 1] = make_float2(acc[t][2] * d1, acc[t][3] * d1);
    }
}

// ---------------------------------------------------------------------------
// FUSED agg1 + GEMM2, 32 rows/block (unchanged round-14 winner)
// ---------------------------------------------------------------------------
__global__ void __launch_bounds__(256, 5)
k_aggemm2(const float* __restrict__ b1, const float* __restrict__ W2, int nrows) {
    __shared__ float2 sW[128 * 20];  // 20KB
    __shared__ float sH[32 * 128];   // 16KB
    __shared__ float sD[32];
    int tid = threadIdx.x;
    int rowBase = blockIdx.x * 32;
    int w = tid >> 5, lane = tid & 31;

    const float2* W2v = (const float2*)W2;
    for (int i = tid; i < 128 * 20; i += 256) sW[i] = W2v[i];

    const float4* xs4 = (const float4*)g_xs;
    float4 bch = ((const float4*)b1)[lane];
    float4* sH4 = (float4*)sH;
#pragma unroll
    for (int r = 0; r < 4; r++) {
        int node = rowBase + w * 4 + r;
        float4 v = make_float4(0.f, 0.f, 0.f, 0.f);
        if (node < nrows) {
            float4 acc = xs4[node * 32 + lane];  // self-loop term
            int e = node * BUCK;
            int end = g_cursor[node];
            int deg = end - e;
            if (end > e + BUCK) end = e + BUCK;
            for (; e + 3 < end; e += 4) {
                int s0 = g_csr[e];
                int s1 = g_csr[e + 1];
                int s2 = g_csr[e + 2];
                int s3 = g_csr[e + 3];
                float4 v0 = xs4[s0 * 32 + lane];
                float4 v1 = xs4[s1 * 32 + lane];
                float4 v2 = xs4[s2 * 32 + lane];
                float4 v3 = xs4[s3 * 32 + lane];
                acc.x += (v0.x + v1.x) + (v2.x + v3.x);
                acc.y += (v0.y + v1.y) + (v2.y + v3.y);
                acc.z += (v0.z + v1.z) + (v2.z + v3.z);
                acc.w += (v0.w + v1.w) + (v2.w + v3.w);
            }
            for (; e < end; e++) {
                float4 vv = xs4[g_csr[e] * 32 + lane];
                acc.x += vv.x; acc.y += vv.y; acc.z += vv.z; acc.w += vv.w;
            }
            float d = rsqrtf((float)(deg + 1));
            if (lane == 0) sD[w * 4 + r] = d;
            v.x = fmaxf(acc.x * d + bch.x, 0.f);
            v.y = fmaxf(acc.y * d + bch.y, 0.f);
            v.z = fmaxf(acc.z * d + bch.z, 0.f);
            v.w = fmaxf(acc.w * d + bch.w, 0.f);
        }
        sH4[(w * 4 + r) * 32 + lane] = v;
    }
    __syncthreads();

    bool act = lane < 20;
    float2 acc2[4];
#pragma unroll
    for (int r = 0; r < 4; r++) acc2[r] = make_float2(0.f, 0.f);

#pragma unroll 4
    for (int k = 0; k < 128; k++) {
        float2 wv = act ? sW[k * 20 + lane] : make_float2(0.f, 0.f);
#pragma unroll
        for (int r = 0; r < 4; r++) {
            float hv = sH[(w * 4 + r) * 128 + k];
            acc2[r].x += hv * wv.x;
            acc2[r].y += hv * wv.y;
        }
    }

    if (act) {
        float2* hs2 = (float2*)g_hs;
#pragma unroll
        for (int r = 0; r < 4; r++) {
            int node = rowBase + w * 4 + r;
            if (node < nrows) {
                float d = sD[w * 4 + r];
                hs2[node * 20 + lane] = make_float2(acc2[r].x * d, acc2[r].y * d);
            }
        }
    }
}

// ---------------------------------------------------------------------------
// Aggregation layer 2 + epilogue (unchanged)
// ---------------------------------------------------------------------------
__global__ void k_agg2(const float* __restrict__ b2, float* __restrict__ out, int n) {
    int t = blockIdx.x * blockDim.x + threadIdx.x;
    if (t >= n * 10) return;
    int node = t / 10;
    int j = t - node * 10;
    const float4* hs4 = (const float4*)g_hs;
    float4 acc = hs4[node * 10 + j];  // self-loop term
    int e = node * BUCK;
    int end = g_cursor[node];
    int deg = end - e;
    if (end > e + BUCK) end = e + BUCK;
    for (; e + 3 < end; e += 4) {
        int s0 = g_csr[e];
        int s1 = g_csr[e + 1];
        int s2 = g_csr[e + 2];
        int s3 = g_csr[e + 3];
        float4 v0 = hs4[s0 * 10 + j];
        float4 v1 = hs4[s1 * 10 + j];
        float4 v2 = hs4[s2 * 10 + j];
        float4 v3 = hs4[s3 * 10 + j];
        acc.x += (v0.x + v1.x) + (v2.x + v3.x);
        acc.y += (v0.y + v1.y) + (v2.y + v3.y);
        acc.z += (v0.z + v1.z) + (v2.z + v3.z);
        acc.w += (v0.w + v1.w) + (v2.w + v3.w);
    }
    for (; e < end; e++) {
        float4 v = hs4[g_csr[e] * 10 + j];
        acc.x += v.x; acc.y += v.y; acc.z += v.z; acc.w += v.w;
    }
    float d = rsqrtf((float)(deg + 1));
    float4 b = ((const float4*)b2)[j];
    ((float4*)out)[t] = make_float4(acc.x * d + b.x, acc.y * d + b.y,
                                    acc.z * d + b.z, acc.w * d + b.w);
}

// ---------------------------------------------------------------------------
extern "C" void kernel_launch(void* const* d_in, const int* in_sizes, int n_in,
                              void* d_out, int out_size) {
    const float* x = (const float*)d_in[0];
    const int* ei = (const int*)d_in[1];   // int32 (jax x64 disabled)
    const float* W1 = (const float*)d_in[2];
    const float* b1 = (const float*)d_in[3];
    const float* W2 = (const float*)d_in[4];
    const float* b2 = (const float*)d_in[5];
    float* out = (float*)d_out;

    int N = in_sizes[0] / 128;  // 50000
    int E = in_sizes[1] / 2;    // 640000

    k_init<<<(N + 255) / 256, 256>>>(N);
    k_fill<<<(E / 2 + 255) / 256, 256>>>(ei, E);
    k_prepW<<<64, 256>>>(W1);

    k_gemm1_mma<<<(N + 63) / 64, 128>>>(x, N);
    k_aggemm2<<<(N + 31) / 32, 256>>>(b1, W2, N);
    k_agg2<<<(N * 10 + 255) / 256, 256>>>(b2, out, N);
}

// round 16
// speedup vs baseline: 1.4103x; 1.4103x over previous
#include <cuda_runtime.h>
#include <cuda_bf16.h>
#include <math.h>
#include <cstdint>

#define NMAX 50000
#define EMAX 640000
#define BUCK 64   // per-node CSR bucket capacity (max degree ~35 for this graph)

// Scratch (static device arrays: allocation-free per harness rules)
__device__ int   g_cursor[NMAX];        // bucket fill cursors; end of row after fill
__device__ int   g_csr[NMAX * BUCK];    // src indices, bucketed by dst
__device__ float g_xs[NMAX * 128];      // (x@W1) * dinv[row]
__device__ float g_hs[NMAX * 40];       // (relu(...)@W2) * dinv[row]
// W1 split-bf16, [half][n][72] padded (stride 72 b16 = 36 words -> banks 4n+qc)
__device__ __align__(16) unsigned short g_Whi[2 * 128 * 72];
__device__ __align__(16) unsigned short g_Wlo[2 * 128 * 72];

// ---------------------------------------------------------------------------
// preamble: init cursors, then scatter edges into per-dst buckets
// ---------------------------------------------------------------------------
__global__ void k_init(int n) {
    int i = blockIdx.x * blockDim.x + threadIdx.x;
    if (i < n) g_cursor[i] = i * BUCK;
}

__global__ void k_fill(const int* __restrict__ ei, int E) {
    int t = blockIdx.x * blockDim.x + threadIdx.x;
    int e0 = t * 2;
    if (e0 >= E) return;
    int e1 = e0 + 1;
    int d0 = ei[E + e0];
    int s0 = ei[e0];
    if (e1 < E) {
        int d1 = ei[E + e1];
        int s1 = ei[e1];
        int p0 = atomicAdd(&g_cursor[d0], 1);
        int p1 = atomicAdd(&g_cursor[d1], 1);
        if (p0 < d0 * BUCK + BUCK) g_csr[p0] = s0;
        if (p1 < d1 * BUCK + BUCK) g_csr[p1] = s1;
    } else {
        int p0 = atomicAdd(&g_cursor[d0], 1);
        if (p0 < d0 * BUCK + BUCK) g_csr[p0] = s0;
    }
}

// ---------------------------------------------------------------------------
// prep: W1[k][n] f32 -> split bf16 hi/lo in padded [k>>6][n][k&63] layout
// ---------------------------------------------------------------------------
__global__ void k_prepW(const float* __restrict__ W) {
    int idx = blockIdx.x * blockDim.x + threadIdx.x;
    if (idx >= 128 * 128) return;
    int k = idx >> 7, n = idx & 127;
    float v = W[idx];
    __nv_bfloat16 h = __float2bfloat16(v);
    __nv_bfloat16 l = __float2bfloat16(v - __bfloat162float(h));
    int a = (k >> 6) * (128 * 72) + n * 72 + (k & 63);
    g_Whi[a] = *(unsigned short*)&h;
    g_Wlo[a] = *(unsigned short*)&l;
}

// ---------------------------------------------------------------------------
// GEMM1 via mma.sync bf16 (split hi/lo, fp32 accum => fp32-level accuracy):
//   xs = (x @ W1) * dinv[row]
// 256 threads / 8 warps; block tile M=64 x N=128; warp tile m16 x n64
// (warps: wm = w>>1 selects 16 rows, wn = w&1 selects 64-col half).
// K processed in two halves of 64 (W half staged in smem, shared by 8 warps).
// ---------------------------------------------------------------------------
__device__ __forceinline__ void mma_bf16(float* c, const uint32_t* a,
                                         uint32_t b0, uint32_t b1) {
    asm volatile(
        "mma.sync.aligned.m16n8k16.row.col.f32.bf16.bf16.f32 "
        "{%0,%1,%2,%3}, {%4,%5,%6,%7}, {%8,%9}, {%0,%1,%2,%3};"
        : "+f"(c[0]), "+f"(c[1]), "+f"(c[2]), "+f"(c[3])
        : "r"(a[0]), "r"(a[1]), "r"(a[2]), "r"(a[3]), "r"(b0), "r"(b1));
}

__device__ __forceinline__ uint32_t cvt_hi(float2 f, float2& rem) {
    __nv_bfloat162 b = __floats2bfloat162_rn(f.x, f.y);
    float2 bf = __bfloat1622float2(b);
    rem = make_float2(f.x - bf.x, f.y - bf.y);
    return *(uint32_t*)&b;
}
__device__ __forceinline__ uint32_t cvt_lo(float2 rem) {
    __nv_bfloat162 b = __floats2bfloat162_rn(rem.x, rem.y);
    return *(uint32_t*)&b;
}

__global__ void __launch_bounds__(256, 3)
k_gemm1_mma(const float* __restrict__ x, int nrows) {
    __shared__ unsigned short sWhi[128 * 72];  // 18KB
    __shared__ unsigned short sWlo[128 * 72];  // 18KB
    int tid = threadIdx.x;
    int w = tid >> 5, lane = tid & 31;
    int wm = w >> 1, wn = w & 1;            // M-group / N-half
    int qr = lane >> 2, qc = lane & 3;      // quad row / col within fragment
    int mBase = blockIdx.x * 64 + wm * 16;
    int row0 = mBase + qr, row1 = row0 + 8;
    bool v0 = row0 < nrows, v1 = row1 < nrows;

    float acc[8][4];
#pragma unroll
    for (int t = 0; t < 8; t++)
#pragma unroll
        for (int i = 0; i < 4; i++) acc[t][i] = 0.f;

    const float2* X2 = (const float2*)x;  // 64 float2 per row

    for (int kh = 0; kh < 2; kh++) {
        if (kh) __syncthreads();
        {   // stage W half into smem (raw uint4 copy of padded layout)
            const uint4* shi = (const uint4*)(g_Whi + kh * (128 * 72));
            const uint4* slo = (const uint4*)(g_Wlo + kh * (128 * 72));
            uint4* dhi = (uint4*)sWhi;
            uint4* dlo = (uint4*)sWlo;
            for (int i = tid; i < 128 * 72 / 8; i += 256) {
                dhi[i] = shi[i];
                dlo[i] = slo[i];
            }
        }
        __syncthreads();

#pragma unroll
        for (int k16 = 0; k16 < 4; k16++) {
            int kb = kh * 64 + k16 * 16;
            int c0 = (kb >> 1) + qc;       // float2 index
            int c1 = c0 + 4;
            float2 f0 = v0 ? X2[row0 * 64 + c0] : make_float2(0.f, 0.f);
            float2 f1 = v1 ? X2[row1 * 64 + c0] : make_float2(0.f, 0.f);
            float2 f2 = v0 ? X2[row0 * 64 + c1] : make_float2(0.f, 0.f);
            float2 f3 = v1 ? X2[row1 * 64 + c1] : make_float2(0.f, 0.f);
            uint32_t ahi[4], alo[4];
            float2 r0, r1, r2, r3;
            ahi[0] = cvt_hi(f0, r0);
            ahi[1] = cvt_hi(f1, r1);
            ahi[2] = cvt_hi(f2, r2);
            ahi[3] = cvt_hi(f3, r3);
            alo[0] = cvt_lo(r0);
            alo[1] = cvt_lo(r1);
            alo[2] = cvt_lo(r2);
            alo[3] = cvt_lo(r3);

            int kk = k16 * 16 + qc * 2;  // b16 offset within half-row
#pragma unroll
            for (int t = 0; t < 8; t++) {
                int n = wn * 64 + t * 8 + qr;
                const unsigned short* ph = sWhi + n * 72 + kk;
                const unsigned short* pl = sWlo + n * 72 + kk;
                uint32_t bh0 = *(const uint32_t*)ph;
                uint32_t bh1 = *(const uint32_t*)(ph + 8);
                uint32_t bl0 = *(const uint32_t*)pl;
                uint32_t bl1 = *(const uint32_t*)(pl + 8);
                mma_bf16(acc[t], ahi, bh0, bh1);
                mma_bf16(acc[t], alo, bh0, bh1);
                mma_bf16(acc[t], ahi, bl0, bl1);
            }
        }
    }

    // epilogue: scale by dinv, store float2s
    float d0 = 0.f, d1 = 0.f;
    if (v0) d0 = rsqrtf((float)(g_cursor[row0] - row0 * BUCK + 1));
    if (v1) d1 = rsqrtf((float)(g_cursor[row1] - row1 * BUCK + 1));
    float2* xs2 = (float2*)g_xs;
#pragma unroll
    for (int t = 0; t < 8; t++) {
        int col = wn * 64 + t * 8 + qc * 2;
        if (v0) xs2[(row0 * 128 + col) >> 1] = make_float2(acc[t][0] * d0, acc[t][1] * d0);
        if (v1) xs2[(row1 * 128 + col) >> 1] = make_float2(acc[t][2] * d1, acc[t][3] * d1);
    }
}

// ---------------------------------------------------------------------------
// FUSED agg1 + GEMM2, 32 rows/block (unchanged round-14 winner)
// ---------------------------------------------------------------------------
__global__ void __launch_bounds__(256, 5)
k_aggemm2(const float* __restrict__ b1, const float* __restrict__ W2, int nrows) {
    __shared__ float2 sW[128 * 20];  // 20KB
    __shared__ float sH[32 * 128];   // 16KB
    __shared__ float sD[32];
    int tid = threadIdx.x;
    int rowBase = blockIdx.x * 32;
    int w = tid >> 5, lane = tid & 31;

    const float2* W2v = (const float2*)W2;
    for (int i = tid; i < 128 * 20; i += 256) sW[i] = W2v[i];

    const float4* xs4 = (const float4*)g_xs;
    float4 bch = ((const float4*)b1)[lane];
    float4* sH4 = (float4*)sH;
#pragma unroll
    for (int r = 0; r < 4; r++) {
        int node = rowBase + w * 4 + r;
        float4 v = make_float4(0.f, 0.f, 0.f, 0.f);
        if (node < nrows) {
            float4 acc = xs4[node * 32 + lane];  // self-loop term
            int e = node * BUCK;
            int end = g_cursor[node];
            int deg = end - e;
            if (end > e + BUCK) end = e + BUCK;
            for (; e + 3 < end; e += 4) {
                int s0 = g_csr[e];
                int s1 = g_csr[e + 1];
                int s2 = g_csr[e + 2];
                int s3 = g_csr[e + 3];
                float4 v0 = xs4[s0 * 32 + lane];
                float4 v1 = xs4[s1 * 32 + lane];
                float4 v2 = xs4[s2 * 32 + lane];
                float4 v3 = xs4[s3 * 32 + lane];
                acc.x += (v0.x + v1.x) + (v2.x + v3.x);
                acc.y += (v0.y + v1.y) + (v2.y + v3.y);
                acc.z += (v0.z + v1.z) + (v2.z + v3.z);
                acc.w += (v0.w + v1.w) + (v2.w + v3.w);
            }
            for (; e < end; e++) {
                float4 vv = xs4[g_csr[e] * 32 + lane];
                acc.x += vv.x; acc.y += vv.y; acc.z += vv.z; acc.w += vv.w;
            }
            float d = rsqrtf((float)(deg + 1));
            if (lane == 0) sD[w * 4 + r] = d;
            v.x = fmaxf(acc.x * d + bch.x, 0.f);
            v.y = fmaxf(acc.y * d + bch.y, 0.f);
            v.z = fmaxf(acc.z * d + bch.z, 0.f);
            v.w = fmaxf(acc.w * d + bch.w, 0.f);
        }
        sH4[(w * 4 + r) * 32 + lane] = v;
    }
    __syncthreads();

    bool act = lane < 20;
    float2 acc2[4];
#pragma unroll
    for (int r = 0; r < 4; r++) acc2[r] = make_float2(0.f, 0.f);

#pragma unroll 4
    for (int k = 0; k < 128; k++) {
        float2 wv = act ? sW[k * 20 + lane] : make_float2(0.f, 0.f);
#pragma unroll
        for (int r = 0; r < 4; r++) {
            float hv = sH[(w * 4 + r) * 128 + k];
            acc2[r].x += hv * wv.x;
            acc2[r].y += hv * wv.y;
        }
    }

    if (act) {
        float2* hs2 = (float2*)g_hs;
#pragma unroll
        for (int r = 0; r < 4; r++) {
            int node = rowBase + w * 4 + r;
            if (node < nrows) {
                float d = sD[w * 4 + r];
                hs2[node * 20 + lane] = make_float2(acc2[r].x * d, acc2[r].y * d);
            }
        }
    }
}

// ---------------------------------------------------------------------------
// Aggregation layer 2 + epilogue (unchanged)
// ---------------------------------------------------------------------------
__global__ void k_agg2(const float* __restrict__ b2, float* __restrict__ out, int n) {
    int t = blockIdx.x * blockDim.x + threadIdx.x;
    if (t >= n * 10) return;
    int node = t / 10;
    int j = t - node * 10;
    const float4* hs4 = (const float4*)g_hs;
    float4 acc = hs4[node * 10 + j];  // self-loop term
    int e = node * BUCK;
    int end = g_cursor[node];
    int deg = end - e;
    if (end > e + BUCK) end = e + BUCK;
    for (; e + 3 < end; e += 4) {
        int s0 = g_csr[e];
        int s1 = g_csr[e + 1];
        int s2 = g_csr[e + 2];
        int s3 = g_csr[e + 3];
        float4 v0 = hs4[s0 * 10 + j];
        float4 v1 = hs4[s1 * 10 + j];
        float4 v2 = hs4[s2 * 10 + j];
        float4 v3 = hs4[s3 * 10 + j];
        acc.x += (v0.x + v1.x) + (v2.x + v3.x);
        acc.y += (v0.y + v1.y) + (v2.y + v3.y);
        acc.z += (v0.z + v1.z) + (v2.z + v3.z);
        acc.w += (v0.w + v1.w) + (v2.w + v3.w);
    }
    for (; e < end; e++) {
        float4 v = hs4[g_csr[e] * 10 + j];
        acc.x += v.x; acc.y += v.y; acc.z += v.z; acc.w += v.w;
    }
    float d = rsqrtf((float)(deg + 1));
    float4 b = ((const float4*)b2)[j];
    ((float4*)out)[t] = make_float4(acc.x * d + b.x, acc.y * d + b.y,
                                    acc.z * d + b.z, acc.w * d + b.w);
}

// ---------------------------------------------------------------------------
extern "C" void kernel_launch(void* const* d_in, const int* in_sizes, int n_in,
                              void* d_out, int out_size) {
    const float* x = (const float*)d_in[0];
    const int* ei = (const int*)d_in[1];   // int32 (jax x64 disabled)
    const float* W1 = (const float*)d_in[2];
    const float* b1 = (const float*)d_in[3];
    const float* W2 = (const float*)d_in[4];
    const float* b2 = (const float*)d_in[5];
    float* out = (float*)d_out;

    int N = in_sizes[0] / 128;  // 50000
    int E = in_sizes[1] / 2;    // 640000

    k_init<<<(N + 255) / 256, 256>>>(N);
    k_fill<<<(E / 2 + 255) / 256, 256>>>(ei, E);
    k_prepW<<<64, 256>>>(W1);

    k_gemm1_mma<<<(N + 63) / 64, 256>>>(x, N);
    k_aggemm2<<<(N + 31) / 32, 256>>>(b1, W2, N);
    k_agg2<<<(N * 10 + 255) / 256, 256>>>(b2, out, N);
}